// round 17
// baseline (speedup 1.0000x reference)
#include <cuda_runtime.h>
#include <stdint.h>

#define N_NODES 100000
#define N_EDGES 600000
#define NODE_IN 387
#define HID 128
#define EDGE_DIM 7
#define EIN 263
#define SCAN_T 512
#define SCAN_NB 196  // 196*512 = 100352 >= N_NODES

// -------- scratch (device globals; no allocation allowed) --------
__device__ float g_agg1[(size_t)N_NODES * NODE_IN];  // reused as P|Q later
__device__ float g_t   [(size_t)N_NODES * HID];
__device__ float g_h1  [(size_t)N_NODES * HID];
__device__ float g_agg2[(size_t)N_NODES * HID];
__device__ float g_h2  [(size_t)N_NODES * HID];
__device__ int   g_is64;
// CSR scratch
__device__ int g_deg[N_NODES];
__device__ int g_bsum[SCAN_NB];
__device__ int g_off[N_NODES + 1];
__device__ int g_cursor[N_NODES];
__device__ int g_bucket[N_EDGES];

__global__ void detect_idx_kernel(const long long* __restrict__ ei)
{
    if (threadIdx.x == 0 && blockIdx.x == 0) {
        int is64 = 1;
        #pragma unroll
        for (int i = 0; i < 16; i++) {
            long long v = ei[i];
            if (v < 0 || v >= (long long)N_NODES) is64 = 0;
        }
        g_is64 = is64;
    }
}

__device__ __forceinline__ void load_edge(const void* ei, int e, int is64, int& s, int& dd)
{
    if (is64) {
        const long long* p = (const long long*)ei;
        s  = (int)__ldg(&p[e]);
        dd = (int)__ldg(&p[N_EDGES + e]);
    } else {
        const int* p = (const int*)ei;
        s  = __ldg(&p[e]);
        dd = __ldg(&p[N_EDGES + e]);
    }
}

__device__ __forceinline__ int load_dst(const void* ei, int e, int is64)
{
    if (is64) return (int)__ldg(&((const long long*)ei)[N_EDGES + e]);
    return __ldg(&((const int*)ei)[N_EDGES + e]);
}

// ======== CSR build ========
__global__ void hist_kernel(const void* __restrict__ ei)
{
    int is64 = g_is64;
    int t = blockIdx.x * blockDim.x + threadIdx.x;
    int nt = gridDim.x * blockDim.x;
    for (int e = t; e < N_EDGES; e += nt)
        atomicAdd(&g_deg[load_dst(ei, e, is64)], 1);
}

__global__ void scan1_kernel()
{
    __shared__ int sarr[SCAN_T];
    int i = blockIdx.x * SCAN_T + threadIdx.x;
    sarr[threadIdx.x] = (i < N_NODES) ? g_deg[i] : 0;
    __syncthreads();
    for (int o = SCAN_T / 2; o > 0; o >>= 1) {
        if (threadIdx.x < o) sarr[threadIdx.x] += sarr[threadIdx.x + o];
        __syncthreads();
    }
    if (threadIdx.x == 0) g_bsum[blockIdx.x] = sarr[0];
}

__global__ void scan2_kernel()
{
    __shared__ int s[SCAN_NB];
    int t = threadIdx.x;
    if (t < SCAN_NB) s[t] = g_bsum[t];
    __syncthreads();
    if (t == 0) {
        int run = 0;
        for (int i = 0; i < SCAN_NB; i++) { int v = s[i]; s[i] = run; run += v; }
        g_off[N_NODES] = N_EDGES;
    }
    __syncthreads();
    if (t < SCAN_NB) g_bsum[t] = s[t];
}

__global__ void scan3_kernel()
{
    __shared__ int sarr[SCAN_T];
    int tid = threadIdx.x;
    int i = blockIdx.x * SCAN_T + tid;
    int v = (i < N_NODES) ? g_deg[i] : 0;
    sarr[tid] = v;
    __syncthreads();
    for (int o = 1; o < SCAN_T; o <<= 1) {
        int t2 = (tid >= o) ? sarr[tid - o] : 0;
        __syncthreads();
        sarr[tid] += t2;
        __syncthreads();
    }
    if (i < N_NODES) g_off[i] = g_bsum[blockIdx.x] + sarr[tid] - v;  // exclusive
}

__global__ void scatter_kernel(const void* __restrict__ ei)
{
    int is64 = g_is64;
    int t = blockIdx.x * blockDim.x + threadIdx.x;
    int nt = gridDim.x * blockDim.x;
    for (int e = t; e < N_EDGES; e += nt) {
        int dd = load_dst(ei, e, is64);
        int pos = atomicAdd(&g_cursor[dd], 1);
        g_bucket[pos] = e;
    }
}

// ======== conv1 aggregation (node-major, no atomics) ========
// agg1[n] = sum_{e: dst=n} relu(x[src_e] + ea_e @ e1_w + e1_b)
__global__ __launch_bounds__(128) void aggregate1_kernel(
    const float* __restrict__ x, const void* __restrict__ ei,
    const float* __restrict__ ea, const float* __restrict__ w,
    const float* __restrict__ b)
{
    __shared__ float sw[EDGE_DIM * NODE_IN];
    __shared__ float sb[NODE_IN];
    for (int i = threadIdx.x; i < EDGE_DIM * NODE_IN; i += 128) sw[i] = w[i];
    for (int i = threadIdx.x; i < NODE_IN; i += 128) sb[i] = b[i];
    __syncthreads();

    int is64 = g_is64;
    int tid = threadIdx.x;
    for (int n = blockIdx.x; n < N_NODES; n += gridDim.x) {
        int beg = g_off[n], end = g_off[n + 1];
        float acc[4] = {0.0f, 0.0f, 0.0f, 0.0f};
        for (int i = beg; i < end; i++) {
            int e = g_bucket[i];
            int s, dd;
            load_edge(ei, e, is64, s, dd);
            const float* ar = ea + (size_t)e * EDGE_DIM;
            float a0 = __ldg(ar + 0), a1 = __ldg(ar + 1), a2 = __ldg(ar + 2);
            float a3 = __ldg(ar + 3), a4 = __ldg(ar + 4), a5 = __ldg(ar + 5);
            float a6 = __ldg(ar + 6);
            const float* xr = x + (size_t)s * NODE_IN;
            #pragma unroll
            for (int c4 = 0; c4 < 4; c4++) {
                int j = tid + c4 * 128;
                if (j < NODE_IN) {
                    float c = sb[j];
                    c = fmaf(a0, sw[0 * NODE_IN + j], c);
                    c = fmaf(a1, sw[1 * NODE_IN + j], c);
                    c = fmaf(a2, sw[2 * NODE_IN + j], c);
                    c = fmaf(a3, sw[3 * NODE_IN + j], c);
                    c = fmaf(a4, sw[4 * NODE_IN + j], c);
                    c = fmaf(a5, sw[5 * NODE_IN + j], c);
                    c = fmaf(a6, sw[6 * NODE_IN + j], c);
                    acc[c4] += fmaxf(__ldg(xr + j) + c, 0.0f);
                }
            }
        }
        float* ag = g_agg1 + (size_t)n * NODE_IN;
        #pragma unroll
        for (int c4 = 0; c4 < 4; c4++) {
            int j = tid + c4 * 128;
            if (j < NODE_IN) ag[j] = acc[c4];
        }
    }
}

// ======== conv2 aggregation (node-major, no atomics) ========
__global__ __launch_bounds__(128) void aggregate2_kernel(
    const float* __restrict__ h1, const void* __restrict__ ei,
    const float* __restrict__ ea, const float* __restrict__ w,
    const float* __restrict__ b)
{
    __shared__ float sw[EDGE_DIM * HID];
    __shared__ float sb[HID];
    for (int i = threadIdx.x; i < EDGE_DIM * HID; i += 128) sw[i] = w[i];
    for (int i = threadIdx.x; i < HID; i += 128) sb[i] = b[i];
    __syncthreads();

    int is64 = g_is64;
    int tid = threadIdx.x;
    for (int n = blockIdx.x; n < N_NODES; n += gridDim.x) {
        int beg = g_off[n], end = g_off[n + 1];
        float acc = 0.0f;
        for (int i = beg; i < end; i++) {
            int e = g_bucket[i];
            int s, dd;
            load_edge(ei, e, is64, s, dd);
            const float* ar = ea + (size_t)e * EDGE_DIM;
            float a0 = __ldg(ar + 0), a1 = __ldg(ar + 1), a2 = __ldg(ar + 2);
            float a3 = __ldg(ar + 3), a4 = __ldg(ar + 4), a5 = __ldg(ar + 5);
            float a6 = __ldg(ar + 6);
            float c = sb[tid];
            c = fmaf(a0, sw[0 * HID + tid], c);
            c = fmaf(a1, sw[1 * HID + tid], c);
            c = fmaf(a2, sw[2 * HID + tid], c);
            c = fmaf(a3, sw[3 * HID + tid], c);
            c = fmaf(a4, sw[4 * HID + tid], c);
            c = fmaf(a5, sw[5 * HID + tid], c);
            c = fmaf(a6, sw[6 * HID + tid], c);
            acc += fmaxf(__ldg(h1 + (size_t)s * HID + tid) + c, 0.0f);
        }
        g_agg2[(size_t)n * HID + tid] = acc;
    }
}

// ================= SGEMM: C[M,128] = act ? relu((A+A2)@B + bias) : (A+A2)@B
__global__ __launch_bounds__(256) void gemm128_kernel(
    const float* __restrict__ A, const float* __restrict__ A2,
    const float* __restrict__ B, const float* __restrict__ bias,
    float* __restrict__ C, int M, int K, int act)
{
    __shared__ __align__(16) float As[2][8][132];
    __shared__ __align__(16) float Bs[2][8][128];
    int tid = threadIdx.x;
    int tx = tid & 15, ty = tid >> 4;
    int mBase = blockIdx.x * 128;
    bool vecA = ((K & 7) == 0);

    float acc[8][8];
    #pragma unroll
    for (int i = 0; i < 8; i++)
        #pragma unroll
        for (int j = 0; j < 8; j++) acc[i][j] = 0.0f;

    {
        if (vecA) {
            int m = tid >> 1, k4 = (tid & 1) * 4;
            int gm = mBase + m;
            float4 v = make_float4(0.0f, 0.0f, 0.0f, 0.0f);
            if (gm < M) {
                size_t idx = (size_t)gm * K + k4;
                v = *(const float4*)(A + idx);
                if (A2) {
                    float4 v2 = *(const float4*)(A2 + idx);
                    v.x += v2.x; v.y += v2.y; v.z += v2.z; v.w += v2.w;
                }
            }
            As[0][k4 + 0][m] = v.x; As[0][k4 + 1][m] = v.y;
            As[0][k4 + 2][m] = v.z; As[0][k4 + 3][m] = v.w;
        } else {
            #pragma unroll
            for (int i = 0; i < 4; i++) {
                int l = tid + 256 * i;
                int m = l >> 3, kk = l & 7;
                int gm = mBase + m, gk = kk;
                float v = 0.0f;
                if (gm < M && gk < K) {
                    size_t idx = (size_t)gm * K + gk;
                    v = __ldg(A + idx);
                    if (A2) v += __ldg(A2 + idx);
                }
                As[0][kk][m] = v;
            }
        }
        int kk = tid >> 5, j4 = (tid & 31) * 4;
        float4 v = make_float4(0.0f, 0.0f, 0.0f, 0.0f);
        if (kk < K) v = *(const float4*)(B + (size_t)kk * 128 + j4);
        *(float4*)&Bs[0][kk][j4] = v;
    }
    __syncthreads();

    int buf = 0;
    for (int k0 = 0; k0 < K; k0 += 8) {
        bool hasNext = (k0 + 8) < K;
        float4 aP = make_float4(0.0f, 0.0f, 0.0f, 0.0f);
        float aPs[4] = {0.0f, 0.0f, 0.0f, 0.0f};
        float4 bP = make_float4(0.0f, 0.0f, 0.0f, 0.0f);
        if (hasNext) {
            int kn = k0 + 8;
            if (vecA) {
                int m = tid >> 1, k4 = (tid & 1) * 4;
                int gm = mBase + m;
                if (gm < M) {
                    size_t idx = (size_t)gm * K + (kn + k4);
                    aP = *(const float4*)(A + idx);
                    if (A2) {
                        float4 v2 = *(const float4*)(A2 + idx);
                        aP.x += v2.x; aP.y += v2.y; aP.z += v2.z; aP.w += v2.w;
                    }
                }
            } else {
                #pragma unroll
                for (int i = 0; i < 4; i++) {
                    int l = tid + 256 * i;
                    int m = l >> 3, kk = l & 7;
                    int gm = mBase + m, gk = kn + kk;
                    if (gm < M && gk < K) {
                        size_t idx = (size_t)gm * K + gk;
                        aPs[i] = __ldg(A + idx);
                        if (A2) aPs[i] += __ldg(A2 + idx);
                    }
                }
            }
            int kk = tid >> 5, j4 = (tid & 31) * 4;
            int gk = kn + kk;
            if (gk < K) bP = *(const float4*)(B + (size_t)gk * 128 + j4);
        }
        #pragma unroll
        for (int kk = 0; kk < 8; kk++) {
            float4 av0 = *(const float4*)&As[buf][kk][ty * 4];
            float4 av1 = *(const float4*)&As[buf][kk][64 + ty * 4];
            float4 bv0 = *(const float4*)&Bs[buf][kk][tx * 4];
            float4 bv1 = *(const float4*)&Bs[buf][kk][64 + tx * 4];
            float a[8] = {av0.x, av0.y, av0.z, av0.w, av1.x, av1.y, av1.z, av1.w};
            float b[8] = {bv0.x, bv0.y, bv0.z, bv0.w, bv1.x, bv1.y, bv1.z, bv1.w};
            #pragma unroll
            for (int i = 0; i < 8; i++)
                #pragma unroll
                for (int j = 0; j < 8; j++)
                    acc[i][j] = fmaf(a[i], b[j], acc[i][j]);
        }
        if (hasNext) {
            int nb = buf ^ 1;
            if (vecA) {
                int m = tid >> 1, k4 = (tid & 1) * 4;
                As[nb][k4 + 0][m] = aP.x; As[nb][k4 + 1][m] = aP.y;
                As[nb][k4 + 2][m] = aP.z; As[nb][k4 + 3][m] = aP.w;
            } else {
                #pragma unroll
                for (int i = 0; i < 4; i++) {
                    int l = tid + 256 * i;
                    int m = l >> 3, kk = l & 7;
                    As[nb][kk][m] = aPs[i];
                }
            }
            int kk = tid >> 5, j4 = (tid & 31) * 4;
            *(float4*)&Bs[nb][kk][j4] = bP;
        }
        __syncthreads();
        buf ^= 1;
    }

    #pragma unroll
    for (int i = 0; i < 8; i++) {
        int rm = (i < 4) ? (ty * 4 + i) : (64 + ty * 4 + i - 4);
        int gr = mBase + rm;
        if (gr >= M) continue;
        #pragma unroll
        for (int j = 0; j < 8; j++) {
            int cn = (j < 4) ? (tx * 4 + j) : (64 + tx * 4 + j - 4);
            float v = acc[i][j];
            if (act) v = fmaxf(v + bias[cn], 0.0f);
            C[(size_t)gr * 128 + cn] = v;
        }
    }
}

// ================= edge final: out[e,:] = relu(P[src]+Q[dst]+ea@W1c+b1) @ W2 + b2
__global__ __launch_bounds__(256) void edge_final_kernel(
    const float* __restrict__ P, const float* __restrict__ Q,
    const void* __restrict__ ei, const float* __restrict__ ea,
    const float* __restrict__ W1, const float* __restrict__ b1,
    const float* __restrict__ W2, const float* __restrict__ b2,
    float* __restrict__ out)
{
    __shared__ float swc[EDGE_DIM * HID];
    __shared__ float sb1[HID];
    __shared__ float sw2[2 * HID];
    for (int i = threadIdx.x; i < EDGE_DIM * HID; i += blockDim.x)
        swc[i] = W1[(size_t)(256 + (i >> 7)) * HID + (i & 127)];
    for (int i = threadIdx.x; i < HID; i += blockDim.x) sb1[i] = b1[i];
    for (int i = threadIdx.x; i < 2 * HID; i += blockDim.x) sw2[i] = W2[i];
    __syncthreads();

    int is64   = g_is64;
    int lane   = threadIdx.x & 31;
    int warp   = (blockIdx.x * blockDim.x + threadIdx.x) >> 5;
    int nwarps = (gridDim.x * blockDim.x) >> 5;
    float bb0 = __ldg(&b2[0]), bb1 = __ldg(&b2[1]);

    for (int e = warp; e < N_EDGES; e += nwarps) {
        int s, dd;
        load_edge(ei, e, is64, s, dd);
        float eav = (lane < EDGE_DIM) ? __ldg(&ea[(size_t)e * EDGE_DIM + lane]) : 0.0f;
        float a0 = __shfl_sync(0xffffffffu, eav, 0);
        float a1 = __shfl_sync(0xffffffffu, eav, 1);
        float a2 = __shfl_sync(0xffffffffu, eav, 2);
        float a3 = __shfl_sync(0xffffffffu, eav, 3);
        float a4 = __shfl_sync(0xffffffffu, eav, 4);
        float a5 = __shfl_sync(0xffffffffu, eav, 5);
        float a6 = __shfl_sync(0xffffffffu, eav, 6);
        float4 pv = __ldg((const float4*)(P + (size_t)s * HID) + lane);
        float4 qv = __ldg((const float4*)(Q + (size_t)dd * HID) + lane);
        int j0 = lane * 4;
        float z0, z1, z2, z3;
        {
            float c0 = sb1[j0 + 0], c1 = sb1[j0 + 1], c2 = sb1[j0 + 2], c3 = sb1[j0 + 3];
            c0 = fmaf(a0, swc[0 * HID + j0 + 0], c0); c1 = fmaf(a0, swc[0 * HID + j0 + 1], c1);
            c2 = fmaf(a0, swc[0 * HID + j0 + 2], c2); c3 = fmaf(a0, swc[0 * HID + j0 + 3], c3);
            c0 = fmaf(a1, swc[1 * HID + j0 + 0], c0); c1 = fmaf(a1, swc[1 * HID + j0 + 1], c1);
            c2 = fmaf(a1, swc[1 * HID + j0 + 2], c2); c3 = fmaf(a1, swc[1 * HID + j0 + 3], c3);
            c0 = fmaf(a2, swc[2 * HID + j0 + 0], c0); c1 = fmaf(a2, swc[2 * HID + j0 + 1], c1);
            c2 = fmaf(a2, swc[2 * HID + j0 + 2], c2); c3 = fmaf(a2, swc[2 * HID + j0 + 3], c3);
            c0 = fmaf(a3, swc[3 * HID + j0 + 0], c0); c1 = fmaf(a3, swc[3 * HID + j0 + 1], c1);
            c2 = fmaf(a3, swc[3 * HID + j0 + 2], c2); c3 = fmaf(a3, swc[3 * HID + j0 + 3], c3);
            c0 = fmaf(a4, swc[4 * HID + j0 + 0], c0); c1 = fmaf(a4, swc[4 * HID + j0 + 1], c1);
            c2 = fmaf(a4, swc[4 * HID + j0 + 2], c2); c3 = fmaf(a4, swc[4 * HID + j0 + 3], c3);
            c0 = fmaf(a5, swc[5 * HID + j0 + 0], c0); c1 = fmaf(a5, swc[5 * HID + j0 + 1], c1);
            c2 = fmaf(a5, swc[5 * HID + j0 + 2], c2); c3 = fmaf(a5, swc[5 * HID + j0 + 3], c3);
            c0 = fmaf(a6, swc[6 * HID + j0 + 0], c0); c1 = fmaf(a6, swc[6 * HID + j0 + 1], c1);
            c2 = fmaf(a6, swc[6 * HID + j0 + 2], c2); c3 = fmaf(a6, swc[6 * HID + j0 + 3], c3);
            z0 = fmaxf(pv.x + qv.x + c0, 0.0f);
            z1 = fmaxf(pv.y + qv.y + c1, 0.0f);
            z2 = fmaxf(pv.z + qv.z + c2, 0.0f);
            z3 = fmaxf(pv.w + qv.w + c3, 0.0f);
        }
        float p0 = z0 * sw2[(j0 + 0) * 2 + 0] + z1 * sw2[(j0 + 1) * 2 + 0]
                 + z2 * sw2[(j0 + 2) * 2 + 0] + z3 * sw2[(j0 + 3) * 2 + 0];
        float p1 = z0 * sw2[(j0 + 0) * 2 + 1] + z1 * sw2[(j0 + 1) * 2 + 1]
                 + z2 * sw2[(j0 + 2) * 2 + 1] + z3 * sw2[(j0 + 3) * 2 + 1];
        #pragma unroll
        for (int off = 16; off > 0; off >>= 1) {
            p0 += __shfl_down_sync(0xffffffffu, p0, off);
            p1 += __shfl_down_sync(0xffffffffu, p1, off);
        }
        if (lane == 0) {
            out[(size_t)e * 2 + 0] = p0 + bb0;
            out[(size_t)e * 2 + 1] = p1 + bb1;
        }
    }
}

extern "C" void kernel_launch(void* const* d_in, const int* in_sizes, int n_in,
                              void* d_out, int out_size)
{
    const float* x     = (const float*)d_in[0];
    const void*  ei    = d_in[1];
    const float* ea    = (const float*)d_in[2];
    const float* e1_w  = (const float*)d_in[3];
    const float* e1_b  = (const float*)d_in[4];
    const float* m1_w1 = (const float*)d_in[5];
    const float* m1_b1 = (const float*)d_in[6];
    const float* m1_w2 = (const float*)d_in[7];
    const float* m1_b2 = (const float*)d_in[8];
    const float* e2_w  = (const float*)d_in[9];
    const float* e2_b  = (const float*)d_in[10];
    const float* m2_w1 = (const float*)d_in[11];
    const float* m2_b1 = (const float*)d_in[12];
    const float* m2_w2 = (const float*)d_in[13];
    const float* m2_b2 = (const float*)d_in[14];
    const float* em_w1 = (const float*)d_in[15];
    const float* em_b1 = (const float*)d_in[16];
    const float* em_w2 = (const float*)d_in[17];
    const float* em_b2 = (const float*)d_in[18];
    float* out = (float*)d_out;

    void *agg1p=nullptr,*agg2p=nullptr,*tp=nullptr,*h1p=nullptr,*h2p=nullptr;
    void *degp=nullptr,*curp=nullptr,*offp=nullptr;
    cudaGetSymbolAddress(&agg1p, g_agg1);
    cudaGetSymbolAddress(&agg2p, g_agg2);
    cudaGetSymbolAddress(&tp, g_t);
    cudaGetSymbolAddress(&h1p, g_h1);
    cudaGetSymbolAddress(&h2p, g_h2);
    cudaGetSymbolAddress(&degp, g_deg);
    cudaGetSymbolAddress(&curp, g_cursor);
    cudaGetSymbolAddress(&offp, g_off);
    float* agg1 = (float*)agg1p;
    float* agg2 = (float*)agg2p;
    float* tbuf = (float*)tp;
    float* h1   = (float*)h1p;
    float* h2   = (float*)h2p;
    float* P = agg1;
    float* Q = agg1 + (size_t)N_NODES * HID;

    const int gblocks = (N_NODES + 127) / 128;   // 782

    detect_idx_kernel<<<1, 32>>>((const long long*)ei);
    // ---- CSR build (dst-major) ----
    cudaMemsetAsync(degp, 0, sizeof(int) * N_NODES, 0);
    hist_kernel<<<592, 256>>>(ei);
    scan1_kernel<<<SCAN_NB, SCAN_T>>>();
    scan2_kernel<<<1, 256>>>();
    scan3_kernel<<<SCAN_NB, SCAN_T>>>();
    cudaMemcpyAsync(curp, offp, sizeof(int) * N_NODES, cudaMemcpyDeviceToDevice, 0);
    scatter_kernel<<<592, 256>>>(ei);
    // ---- conv1 ----
    aggregate1_kernel<<<1480, 128>>>(x, ei, ea, e1_w, e1_b);
    gemm128_kernel<<<gblocks, 256>>>(x, agg1, m1_w1, m1_b1, tbuf, N_NODES, NODE_IN, 1);
    gemm128_kernel<<<gblocks, 256>>>(tbuf, nullptr, m1_w2, m1_b2, h1, N_NODES, HID, 1);
    // ---- conv2 ----
    aggregate2_kernel<<<1480, 128>>>(h1, ei, ea, e2_w, e2_b);
    gemm128_kernel<<<gblocks, 256>>>(h1, agg2, m2_w1, m2_b1, tbuf, N_NODES, HID, 1);
    gemm128_kernel<<<gblocks, 256>>>(tbuf, nullptr, m2_w2, m2_b2, h2, N_NODES, HID, 1);
    // ---- edge MLP (factorized) ----
    gemm128_kernel<<<gblocks, 256>>>(h2, nullptr, em_w1, em_b1, P, N_NODES, HID, 0);
    gemm128_kernel<<<gblocks, 256>>>(h2, nullptr, em_w1 + (size_t)128 * HID, em_b1, Q, N_NODES, HID, 0);
    edge_final_kernel<<<1480, 256>>>(P, Q, ei, ea, em_w1, em_b1, em_w2, em_b2, out);
}